// round 3
// baseline (speedup 1.0000x reference)
#include <cuda_runtime.h>
#include <cstddef>

#define IMG_W 256
#define IMG_H 256
#define RPB   64               // output rows per warp-strip
#define STEPS (RPB + 8)        // input rows S-4 .. S+RPB+3

// edge = conv(x,K5)+conv(x,K3) == 2.2*x - 0.19*box3(x) - 0.01*box5(x)
// out  = |maxpool5x5_s1_p2(edge)|   (separable; -inf pool padding)
//
// One warp per (plane, 64-row strip); lane owns 8 columns (warp covers the
// full 256-col width). Horizontal halos via warp shuffles; vertical state in
// shift chains / mod-5 ring (all static after unroll-by-5). 128-thread blocks
// so all 4 SMSPs are used (wid%4 mapping).

__global__ void __launch_bounds__(128, 3)
fused_edge_pool(const float* __restrict__ x, float* __restrict__ out)
{
    const int lane  = threadIdx.x & 31;
    const int g     = blockIdx.x * 4 + (threadIdx.x >> 5);   // 0..2047
    const int plane = g >> 2;                                // 512 planes
    const int S     = (g & 3) * RPB;                         // 4 strips/plane
    const int c0    = lane << 3;

    const float* __restrict__ xp = x   + (size_t)plane * (IMG_H * IMG_W) + c0;
    float*       __restrict__ op = out + (size_t)plane * (IMG_H * IMG_W) + c0;

    const float    NINF = __int_as_float(0xff800000);
    const unsigned FULL = 0xffffffffu;

    // h5 ring (depth 5, mod-5 static indices); h3/x as shift chains;
    // vertical max as pair-max chain P1..P3 + hm_prev.
    float h5r[5][8];
    float h3_1[8], h3_2[8], h3_3[8];   // h3 of rows rin-1, rin-2, rin-3
    float x_1[8], x_2[8];              // x of rows rin-1, rin-2
    float hm_prev[8], P1[8], P2[8], P3[8];
#pragma unroll
    for (int j = 0; j < 8; ++j) {
        h3_1[j] = h3_2[j] = h3_3[j] = 0.f;
        x_1[j] = x_2[j] = 0.f;
        hm_prev[j] = P1[j] = P2[j] = P3[j] = NINF;
    }
#pragma unroll
    for (int i = 0; i < 5; ++i)
#pragma unroll
        for (int j = 0; j < 8; ++j) h5r[i][j] = 0.f;

    // 3-deep prefetch shift chain.
    float4 n1a, n1b, n2a, n2b, n3a, n3b;
    {
        const float4 z = make_float4(0.f, 0.f, 0.f, 0.f);
        int r0 = S - 4, r1 = S - 3, r2 = S - 2;
        n1a = ((unsigned)r0 < IMG_H) ? *reinterpret_cast<const float4*>(xp + r0 * IMG_W)     : z;
        n1b = ((unsigned)r0 < IMG_H) ? *reinterpret_cast<const float4*>(xp + r0 * IMG_W + 4) : z;
        n2a = ((unsigned)r1 < IMG_H) ? *reinterpret_cast<const float4*>(xp + r1 * IMG_W)     : z;
        n2b = ((unsigned)r1 < IMG_H) ? *reinterpret_cast<const float4*>(xp + r1 * IMG_W + 4) : z;
        n3a = ((unsigned)r2 < IMG_H) ? *reinterpret_cast<const float4*>(xp + r2 * IMG_W)     : z;
        n3b = ((unsigned)r2 < IMG_H) ? *reinterpret_cast<const float4*>(xp + r2 * IMG_W + 4) : z;
    }

#pragma unroll 1
    for (int ss = 0; ss < STEPS; ss += 5) {
#pragma unroll
        for (int k = 0; k < 5; ++k) {
            const int s = ss + k;
            if (s >= STEPS) break;          // uniform across warp
            const int rin = S - 4 + s;      // input row consumed this step

            const float4 xa = n1a, xb = n1b;
            n1a = n2a; n1b = n2b; n2a = n3a; n2b = n3b;
            {
                const int rl = rin + 3;     // prefetch distance 3
                const bool v = ((unsigned)rl < IMG_H) && (s + 3 < STEPS);
                const float4 z = make_float4(0.f, 0.f, 0.f, 0.f);
                n3a = v ? *reinterpret_cast<const float4*>(xp + rl * IMG_W)     : z;
                n3b = v ? *reinterpret_cast<const float4*>(xp + rl * IMG_W + 4) : z;
            }

            // ---- horizontal box sums of row rin (halo via shuffles) ----
            float w[12];
            w[2] = xa.x; w[3] = xa.y; w[4] = xa.z; w[5] = xa.w;
            w[6] = xb.x; w[7] = xb.y; w[8] = xb.z; w[9] = xb.w;
            w[0]  = __shfl_up_sync(FULL, xb.z, 1);
            w[1]  = __shfl_up_sync(FULL, xb.w, 1);
            w[10] = __shfl_down_sync(FULL, xa.x, 1);
            w[11] = __shfl_down_sync(FULL, xa.y, 1);
            if (lane == 0)  { w[0]  = 0.f; w[1]  = 0.f; }   // conv zero pad
            if (lane == 31) { w[10] = 0.f; w[11] = 0.f; }

            float h3n[8];
#pragma unroll
            for (int j = 0; j < 8; ++j) {
                const float a3 = w[j + 1] + w[j + 2] + w[j + 3];
                h3n[j] = a3;
                h5r[k][j] = a3 + w[j] + w[j + 4];
            }

            // ---- edge row re = rin-2 (vertical sums; uses pre-shift chains) ----
            float e[8];
#pragma unroll
            for (int j = 0; j < 8; ++j) {
                const float s3 = h3_1[j] + h3_2[j] + h3_3[j];                 // rows rin-1..rin-3
                const float s5 = (h5r[0][j] + h5r[1][j]) + (h5r[2][j] + h5r[3][j]) + h5r[4][j];
                e[j] = 2.2f * x_2[j] - 0.19f * s3 - 0.01f * s5;
            }

            // shift chains (renamed away in unrolled code)
#pragma unroll
            for (int j = 0; j < 8; ++j) {
                h3_3[j] = h3_2[j]; h3_2[j] = h3_1[j]; h3_1[j] = h3n[j];
                x_2[j]  = x_1[j];  x_1[j]  = w[j + 2];
            }

            // ---- horizontal 5-max of edge row (pair tree) ----
            float q[12];
            q[0]  = __shfl_up_sync(FULL, e[6], 1);
            q[1]  = __shfl_up_sync(FULL, e[7], 1);
            q[10] = __shfl_down_sync(FULL, e[0], 1);
            q[11] = __shfl_down_sync(FULL, e[1], 1);
            if (lane == 0)  { q[0]  = NINF; q[1]  = NINF; }   // pool -inf pad
            if (lane == 31) { q[10] = NINF; q[11] = NINF; }
#pragma unroll
            for (int j = 0; j < 8; ++j) q[j + 2] = e[j];

            float pm[10];
#pragma unroll
            for (int i = 0; i < 10; ++i) pm[i] = fmaxf(q[i], q[i + 1]);

            const int  re  = rin - 2;
            const bool val = (re >= 0 && re < IMG_H);
            float hm[8];
#pragma unroll
            for (int j = 0; j < 8; ++j) {
                const float m = fmaxf(fmaxf(pm[j], pm[j + 2]), q[j + 4]);
                hm[j] = val ? m : NINF;
            }

            // ---- vertical 5-max via pair chain + abs, output row r = rin-4 ----
            if (s >= 8) {
                const int r = rin - 4;
                float o[8];
#pragma unroll
                for (int j = 0; j < 8; ++j)
                    o[j] = fabsf(fmaxf(fmaxf(P3[j], P1[j]), hm[j]));
                *reinterpret_cast<float4*>(op + r * IMG_W)     = make_float4(o[0], o[1], o[2], o[3]);
                *reinterpret_cast<float4*>(op + r * IMG_W + 4) = make_float4(o[4], o[5], o[6], o[7]);
            }
#pragma unroll
            for (int j = 0; j < 8; ++j) {
                P3[j] = P2[j]; P2[j] = P1[j];
                P1[j] = fmaxf(hm_prev[j], hm[j]);
                hm_prev[j] = hm[j];
            }
        }
    }
}

extern "C" void kernel_launch(void* const* d_in, const int* in_sizes, int n_in,
                              void* d_out, int out_size)
{
    const float* x = (const float*)d_in[0];
    float* out = (float*)d_out;
    const int planes = in_sizes[0] / (IMG_H * IMG_W);          // 512
    const int warps  = planes * (IMG_H / RPB);                 // 2048
    fused_edge_pool<<<warps / 4, 128>>>(x, out);               // 4 warps/block
}

// round 4
// speedup vs baseline: 1.6679x; 1.6679x over previous
#include <cuda_runtime.h>
#include <cstddef>

#define IMG_W 256
#define IMG_H 256
#define RPB   64               // output rows per warp-strip
#define STEPS (RPB + 8)        // input rows S-4 .. S+RPB+3

// edge = conv(x,K5)+conv(x,K3) == 2.2*x - 0.19*box3(x) - 0.01*box5(x)
// out  = |maxpool5x5_s1_p2(edge)|   (separable; -inf pool padding)
//
// Vertical-first separable scheme: only the raw input ring (5 rows x 8 cols)
// is persistent; vertical box sums v3/v5 come straight from the ring, then
// horizontal sums of v3/v5 are transient (shuffle halos, no rings). This cuts
// per-thread state ~35% vs horizontal-first so nothing spills to local.

__global__ void __launch_bounds__(128)
fused_edge_pool(const float* __restrict__ x, float* __restrict__ out)
{
    const int lane  = threadIdx.x & 31;
    const int g     = blockIdx.x * 4 + (threadIdx.x >> 5);   // 0..2047
    const int plane = g >> 2;                                // 512 planes
    const int S     = (g & 3) * RPB;                         // 4 strips/plane
    const int c0    = lane << 3;

    const float* __restrict__ xp = x   + (size_t)plane * (IMG_H * IMG_W) + c0;
    float*       __restrict__ op = out + (size_t)plane * (IMG_H * IMG_W) + c0;

    const float    NINF = __int_as_float(0xff800000);
    const unsigned FULL = 0xffffffffu;

    // Input ring: rows rin-4..rin, slot = row mod 5 (static via unroll-by-5).
    float xr[5][8];
#pragma unroll
    for (int i = 0; i < 5; ++i)
#pragma unroll
        for (int j = 0; j < 8; ++j) xr[i][j] = 0.f;

    // Vertical 5-max pair chain.
    float hm_prev[8], P1[8], P2[8], P3[8];
#pragma unroll
    for (int j = 0; j < 8; ++j) { hm_prev[j] = P1[j] = P2[j] = P3[j] = NINF; }

    // 3-deep prefetch shift chain.
    float4 n1a, n1b, n2a, n2b, n3a, n3b;
    {
        const float4 z = make_float4(0.f, 0.f, 0.f, 0.f);
        int r0 = S - 4, r1 = S - 3, r2 = S - 2;
        n1a = ((unsigned)r0 < IMG_H) ? *reinterpret_cast<const float4*>(xp + r0 * IMG_W)     : z;
        n1b = ((unsigned)r0 < IMG_H) ? *reinterpret_cast<const float4*>(xp + r0 * IMG_W + 4) : z;
        n2a = ((unsigned)r1 < IMG_H) ? *reinterpret_cast<const float4*>(xp + r1 * IMG_W)     : z;
        n2b = ((unsigned)r1 < IMG_H) ? *reinterpret_cast<const float4*>(xp + r1 * IMG_W + 4) : z;
        n3a = ((unsigned)r2 < IMG_H) ? *reinterpret_cast<const float4*>(xp + r2 * IMG_W)     : z;
        n3b = ((unsigned)r2 < IMG_H) ? *reinterpret_cast<const float4*>(xp + r2 * IMG_W + 4) : z;
    }

#pragma unroll 1
    for (int ss = 0; ss < STEPS; ss += 5) {
#pragma unroll
        for (int k = 0; k < 5; ++k) {
            const int s = ss + k;
            if (s >= STEPS) break;          // uniform across warp
            const int rin = S - 4 + s;      // input row consumed this step

            const float4 xa = n1a, xb = n1b;
            n1a = n2a; n1b = n2b; n2a = n3a; n2b = n3b;
            {
                const int rl = rin + 3;     // prefetch distance 3
                const bool v = ((unsigned)rl < IMG_H) && (s + 3 < STEPS);
                const float4 z = make_float4(0.f, 0.f, 0.f, 0.f);
                n3a = v ? *reinterpret_cast<const float4*>(xp + rl * IMG_W)     : z;
                n3b = v ? *reinterpret_cast<const float4*>(xp + rl * IMG_W + 4) : z;
            }

            // ---- write ring slot k (row rin) ----
            xr[k][0] = xa.x; xr[k][1] = xa.y; xr[k][2] = xa.z; xr[k][3] = xa.w;
            xr[k][4] = xb.x; xr[k][5] = xb.y; xr[k][6] = xb.z; xr[k][7] = xb.w;

            // ---- vertical box sums for edge row re = rin-2 ----
            // row rin-d lives in slot (k-d+5)%5
            const int a1 = (k + 4) % 5;   // rin-1
            const int a2 = (k + 3) % 5;   // rin-2 (center)
            const int a3 = (k + 2) % 5;   // rin-3
            const int a4 = (k + 1) % 5;   // rin-4
            float v3[8], v5[8];
#pragma unroll
            for (int j = 0; j < 8; ++j) {
                const float t3 = xr[a1][j] + xr[a2][j] + xr[a3][j];
                v3[j] = t3;
                v5[j] = t3 + xr[k][j] + xr[a4][j];
            }

            // ---- horizontal sums of v3 (+-1) and v5 (+-2); halos via shuffles ----
            float v3l = __shfl_up_sync(FULL, v3[7], 1);     // col c0-1
            float v3r = __shfl_down_sync(FULL, v3[0], 1);   // col c0+8
            float v5l1 = __shfl_up_sync(FULL, v5[6], 1);    // col c0-2
            float v5l0 = __shfl_up_sync(FULL, v5[7], 1);    // col c0-1
            float v5r0 = __shfl_down_sync(FULL, v5[0], 1);  // col c0+8
            float v5r1 = __shfl_down_sync(FULL, v5[1], 1);  // col c0+9
            if (lane == 0)  { v3l = 0.f; v5l1 = 0.f; v5l0 = 0.f; }   // conv zero pad
            if (lane == 31) { v3r = 0.f; v5r0 = 0.f; v5r1 = 0.f; }

            float v3e[10];
            v3e[0] = v3l;
#pragma unroll
            for (int j = 0; j < 8; ++j) v3e[j + 1] = v3[j];
            v3e[9] = v3r;

            float v5e[12];
            v5e[0] = v5l1; v5e[1] = v5l0;
#pragma unroll
            for (int j = 0; j < 8; ++j) v5e[j + 2] = v5[j];
            v5e[10] = v5r0; v5e[11] = v5r1;

            float pm5[10];
#pragma unroll
            for (int i = 0; i < 10; ++i) pm5[i] = v5e[i] + v5e[i + 1];

            // ---- edge row e (center tap = ring slot a2) ----
            float e[8];
#pragma unroll
            for (int j = 0; j < 8; ++j) {
                const float h3 = v3e[j] + v3e[j + 1] + v3e[j + 2];
                const float h5 = pm5[j] + pm5[j + 2] + v5e[j + 4];
                e[j] = fmaf(2.2f, xr[a2][j], fmaf(-0.19f, h3, -0.01f * h5));
            }

            // ---- horizontal 5-max of edge row ----
            float q[12];
            q[0]  = __shfl_up_sync(FULL, e[6], 1);
            q[1]  = __shfl_up_sync(FULL, e[7], 1);
            q[10] = __shfl_down_sync(FULL, e[0], 1);
            q[11] = __shfl_down_sync(FULL, e[1], 1);
            if (lane == 0)  { q[0]  = NINF; q[1]  = NINF; }   // pool -inf pad
            if (lane == 31) { q[10] = NINF; q[11] = NINF; }
#pragma unroll
            for (int j = 0; j < 8; ++j) q[j + 2] = e[j];

            float pm[10];
#pragma unroll
            for (int i = 0; i < 10; ++i) pm[i] = fmaxf(q[i], q[i + 1]);

            const int  re  = rin - 2;
            const bool val = (re >= 0 && re < IMG_H);
            float hm[8];
#pragma unroll
            for (int j = 0; j < 8; ++j) {
                const float m = fmaxf(fmaxf(pm[j], pm[j + 2]), q[j + 4]);
                hm[j] = val ? m : NINF;
            }

            // ---- vertical 5-max via pair chain + abs, output row r = rin-4 ----
            if (s >= 8) {
                const int r = rin - 4;
                float o[8];
#pragma unroll
                for (int j = 0; j < 8; ++j)
                    o[j] = fabsf(fmaxf(fmaxf(P3[j], P1[j]), hm[j]));
                *reinterpret_cast<float4*>(op + r * IMG_W)     = make_float4(o[0], o[1], o[2], o[3]);
                *reinterpret_cast<float4*>(op + r * IMG_W + 4) = make_float4(o[4], o[5], o[6], o[7]);
            }
#pragma unroll
            for (int j = 0; j < 8; ++j) {
                P3[j] = P2[j]; P2[j] = P1[j];
                P1[j] = fmaxf(hm_prev[j], hm[j]);
                hm_prev[j] = hm[j];
            }
        }
    }
}

extern "C" void kernel_launch(void* const* d_in, const int* in_sizes, int n_in,
                              void* d_out, int out_size)
{
    const float* x = (const float*)d_in[0];
    float* out = (float*)d_out;
    const int planes = in_sizes[0] / (IMG_H * IMG_W);          // 512
    const int warps  = planes * (IMG_H / RPB);                 // 2048
    fused_edge_pool<<<warps / 4, 128>>>(x, out);               // 4 warps/block
}

// round 5
// speedup vs baseline: 1.9490x; 1.1686x over previous
#include <cuda_runtime.h>
#include <cstddef>

#define IMG_W 256
#define IMG_H 256
#define RPB   64               // output rows per warp-strip
#define STEPS (RPB + 8)        // input rows S-4 .. S+RPB+3

// edge = conv(x,K5)+conv(x,K3) == 2.2*x - 0.19*box3(x) - 0.01*box5(x)
// out  = |maxpool5x5_s1_p2(edge)|   (separable; -inf pool padding)
//
// Vertical-first separable scheme; only the raw input ring (5x8) plus the
// pool pair-chain (4x8) and a 2-deep prefetch persist per thread (~88 floats).
// Reg-capped to 128 (launch_bounds 128,4) -> 4 blocks/SM, 16 warps resident,
// grid 512 fits in ONE wave (capacity 592).

__global__ void __launch_bounds__(128, 4)
fused_edge_pool(const float* __restrict__ x, float* __restrict__ out)
{
    const int lane  = threadIdx.x & 31;
    const int g     = blockIdx.x * 4 + (threadIdx.x >> 5);   // 0..2047
    const int plane = g >> 2;                                // 512 planes
    const int S     = (g & 3) * RPB;                         // 4 strips/plane
    const int c0    = lane << 3;

    const float* __restrict__ xp = x   + (size_t)plane * (IMG_H * IMG_W) + c0;
    float*       __restrict__ op = out + (size_t)plane * (IMG_H * IMG_W) + c0;

    const float    NINF = __int_as_float(0xff800000);
    const unsigned FULL = 0xffffffffu;

    // Input ring: rows rin-4..rin, slot = row mod 5 (static via unroll-by-5).
    float xr[5][8];
#pragma unroll
    for (int i = 0; i < 5; ++i)
#pragma unroll
        for (int j = 0; j < 8; ++j) xr[i][j] = 0.f;

    // Vertical 5-max pair chain: out(r) = max(P(r), P(r+2), hm(r+4)),
    // P(m) = max(hm(m), hm(m+1)).
    float hm_prev[8], P1[8], P2[8], P3[8];
#pragma unroll
    for (int j = 0; j < 8; ++j) { hm_prev[j] = P1[j] = P2[j] = P3[j] = NINF; }

    // 2-deep prefetch shift chain.
    float4 n0a, n0b, n1a, n1b;
    {
        const float4 z = make_float4(0.f, 0.f, 0.f, 0.f);
        int r0 = S - 4, r1 = S - 3;
        n0a = ((unsigned)r0 < IMG_H) ? *reinterpret_cast<const float4*>(xp + r0 * IMG_W)     : z;
        n0b = ((unsigned)r0 < IMG_H) ? *reinterpret_cast<const float4*>(xp + r0 * IMG_W + 4) : z;
        n1a = ((unsigned)r1 < IMG_H) ? *reinterpret_cast<const float4*>(xp + r1 * IMG_W)     : z;
        n1b = ((unsigned)r1 < IMG_H) ? *reinterpret_cast<const float4*>(xp + r1 * IMG_W + 4) : z;
    }

#pragma unroll 1
    for (int ss = 0; ss < STEPS; ss += 5) {
#pragma unroll
        for (int k = 0; k < 5; ++k) {
            const int s = ss + k;
            if (s >= STEPS) break;          // uniform across warp
            const int rin = S - 4 + s;      // input row consumed this step

            const float4 xa = n0a, xb = n0b;
            n0a = n1a; n0b = n1b;
            {
                const int rl = rin + 2;     // prefetch distance 2
                const bool v = ((unsigned)rl < IMG_H) && (s + 2 < STEPS);
                const float4 z = make_float4(0.f, 0.f, 0.f, 0.f);
                n1a = v ? *reinterpret_cast<const float4*>(xp + rl * IMG_W)     : z;
                n1b = v ? *reinterpret_cast<const float4*>(xp + rl * IMG_W + 4) : z;
            }

            // ---- write ring slot k (row rin) ----
            xr[k][0] = xa.x; xr[k][1] = xa.y; xr[k][2] = xa.z; xr[k][3] = xa.w;
            xr[k][4] = xb.x; xr[k][5] = xb.y; xr[k][6] = xb.z; xr[k][7] = xb.w;

            // ---- vertical box sums for edge row re = rin-2 ----
            const int a1 = (k + 4) % 5;   // rin-1
            const int a2 = (k + 3) % 5;   // rin-2 (center)
            const int a3 = (k + 2) % 5;   // rin-3
            const int a4 = (k + 1) % 5;   // rin-4
            float v3[8], v5[8];
#pragma unroll
            for (int j = 0; j < 8; ++j) {
                const float t3 = xr[a1][j] + xr[a2][j] + xr[a3][j];
                v3[j] = t3;
                v5[j] = t3 + xr[k][j] + xr[a4][j];
            }

            // ---- horizontal halos of v3 (+-1) and v5 (+-2) via shuffles ----
            float v3l  = __shfl_up_sync(FULL, v3[7], 1);
            float v3r  = __shfl_down_sync(FULL, v3[0], 1);
            float v5l1 = __shfl_up_sync(FULL, v5[6], 1);
            float v5l0 = __shfl_up_sync(FULL, v5[7], 1);
            float v5r0 = __shfl_down_sync(FULL, v5[0], 1);
            float v5r1 = __shfl_down_sync(FULL, v5[1], 1);
            if (lane == 0)  { v3l = 0.f; v5l1 = 0.f; v5l0 = 0.f; }   // conv zero pad
            if (lane == 31) { v3r = 0.f; v5r0 = 0.f; v5r1 = 0.f; }

            float v3e[10];
            v3e[0] = v3l;
#pragma unroll
            for (int j = 0; j < 8; ++j) v3e[j + 1] = v3[j];
            v3e[9] = v3r;

            float v5e[12];
            v5e[0] = v5l1; v5e[1] = v5l0;
#pragma unroll
            for (int j = 0; j < 8; ++j) v5e[j + 2] = v5[j];
            v5e[10] = v5r0; v5e[11] = v5r1;

            float pm5[10];
#pragma unroll
            for (int i = 0; i < 10; ++i) pm5[i] = v5e[i] + v5e[i + 1];

            // ---- edge row ----
            float e[8];
#pragma unroll
            for (int j = 0; j < 8; ++j) {
                const float h3 = v3e[j] + v3e[j + 1] + v3e[j + 2];
                const float h5 = pm5[j] + pm5[j + 2] + v5e[j + 4];
                e[j] = fmaf(2.2f, xr[a2][j], fmaf(-0.19f, h3, -0.01f * h5));
            }

            // ---- horizontal 5-max of edge row ----
            float q[12];
            q[0]  = __shfl_up_sync(FULL, e[6], 1);
            q[1]  = __shfl_up_sync(FULL, e[7], 1);
            q[10] = __shfl_down_sync(FULL, e[0], 1);
            q[11] = __shfl_down_sync(FULL, e[1], 1);
            if (lane == 0)  { q[0]  = NINF; q[1]  = NINF; }   // pool -inf pad
            if (lane == 31) { q[10] = NINF; q[11] = NINF; }
#pragma unroll
            for (int j = 0; j < 8; ++j) q[j + 2] = e[j];

            float hm[8];
            const int re = rin - 2;
            if (re >= 0 && re < IMG_H) {     // warp-uniform; false only at strip edges
                float pm[10];
#pragma unroll
                for (int i = 0; i < 10; ++i) pm[i] = fmaxf(q[i], q[i + 1]);
#pragma unroll
                for (int j = 0; j < 8; ++j)
                    hm[j] = fmaxf(fmaxf(pm[j], pm[j + 2]), q[j + 4]);
            } else {
#pragma unroll
                for (int j = 0; j < 8; ++j) hm[j] = NINF;
            }

            // ---- vertical 5-max via pair chain + abs, output row r = rin-4 ----
            if (s >= 8) {
                const int r = rin - 4;
                float o[8];
#pragma unroll
                for (int j = 0; j < 8; ++j)
                    o[j] = fabsf(fmaxf(fmaxf(P3[j], P1[j]), hm[j]));
                *reinterpret_cast<float4*>(op + r * IMG_W)     = make_float4(o[0], o[1], o[2], o[3]);
                *reinterpret_cast<float4*>(op + r * IMG_W + 4) = make_float4(o[4], o[5], o[6], o[7]);
            }
#pragma unroll
            for (int j = 0; j < 8; ++j) {
                P3[j] = P2[j]; P2[j] = P1[j];
                P1[j] = fmaxf(hm_prev[j], hm[j]);
                hm_prev[j] = hm[j];
            }
        }
    }
}

extern "C" void kernel_launch(void* const* d_in, const int* in_sizes, int n_in,
                              void* d_out, int out_size)
{
    const float* x = (const float*)d_in[0];
    float* out = (float*)d_out;
    const int planes = in_sizes[0] / (IMG_H * IMG_W);          // 512
    const int warps  = planes * (IMG_H / RPB);                 // 2048
    fused_edge_pool<<<warps / 4, 128>>>(x, out);               // 512 blocks, 1 wave
}